// round 4
// baseline (speedup 1.0000x reference)
#include <cuda_runtime.h>
#include <cstdint>

#define BATCH 32
#define HDIM 512
#define WDIM 512
#define NPIX (HDIM * WDIM)
#define KTOP 1000
#define MAXCAND 65536

// -------- static device scratch (no allocations allowed) --------
__device__ unsigned long long g_cand[BATCH][MAXCAND];
__device__ int g_cnt[BATCH];
__device__ unsigned long long g_top[BATCH][1024];
__device__ int g_topk[BATCH];

// -------- XLA:CPU GenerateVF32Exp (llvm_ir_runtime.cc), Eigen/Cephes style --------
// Non-FMA variant: VectorSupportLibrary::MulAdd = separate fmul + fadd,
// no contraction without fast-math flags. All ops forced round-to-nearest.
__device__ __forceinline__ float xla_cpu_expf(float x) {
    const float exp_hi = 88.3762626647950f;
    const float exp_lo = -88.3762626647949f;
    const float log2ef = 1.44269504088896341f;
    const float c1 = 0.693359375f;
    const float c2 = -2.12194440e-4f;

    float xc = fminf(fmaxf(x, exp_lo), exp_hi);
    float fx = floorf(__fadd_rn(__fmul_rn(xc, log2ef), 0.5f));
    float tmp = __fmul_rn(c1, fx);
    float z = __fmul_rn(c2, fx);
    float r = __fsub_rn(xc, tmp);
    r = __fsub_rn(r, z);
    z = __fmul_rn(r, r);

    float y = 1.9875691500E-4f;
    y = __fadd_rn(__fmul_rn(y, r), 1.3981999507E-3f);
    y = __fadd_rn(__fmul_rn(y, r), 8.3334519073E-3f);
    y = __fadd_rn(__fmul_rn(y, r), 4.1665795894E-2f);
    y = __fadd_rn(__fmul_rn(y, r), 1.6666665459E-1f);
    y = __fadd_rn(__fmul_rn(y, r), 5.0000001201E-1f);
    y = __fadd_rn(__fmul_rn(y, z), r);
    y = __fadd_rn(y, 1.0f);

    int emm0 = (((int)fx) + 0x7f) << 23;   // fx integral & clamped
    return __fmul_rn(y, __int_as_float(emm0));
}

__device__ __forceinline__ float xla_sigmoidf(float x) {
    float e = xla_cpu_expf(-x);
    return __fdiv_rn(1.0f, __fadd_rn(1.0f, e));
}

__device__ __forceinline__ float score_fn(float r, float u) {
    float s  = xla_sigmoidf(r);
    float p  = __fmul_rn(s, s);                         // pow(x,2) -> x*x
    float su = xla_sigmoidf(u);
    float m  = __fsub_rn(1.0f, __fmul_rn(0.35f, su));   // separate HLO ops
    return __fmul_rn(p, m);
}

// -------- kernel 0: reset counters --------
__global__ void zero_cnt_kernel() {
    if (threadIdx.x < BATCH) g_cnt[threadIdx.x] = 0;
}

// -------- kernel 1: fused score + 3x3 NMS + candidate compaction --------
__global__ __launch_bounds__(256) void peaks_kernel(const float* __restrict__ route,
                                                    const float* __restrict__ unc) {
    __shared__ float sc[34][35];
    __shared__ unsigned long long sbuf[1024];
    __shared__ int scnt;
    __shared__ int sbase;

    int b = blockIdx.z;
    int tx0 = blockIdx.x * 32;
    int ty0 = blockIdx.y * 32;
    const float* rp = route + (size_t)b * NPIX;
    const float* up = unc + (size_t)b * NPIX;
    int tid = threadIdx.x;

    if (tid == 0) scnt = 0;

    // fill 34x34 halo tile of scores
    for (int i = tid; i < 34 * 34; i += 256) {
        int ly = i / 34, lx = i % 34;
        int gx = tx0 - 1 + lx;
        int gy = ty0 - 1 + ly;
        float v = -1e30f;
        if (gx >= 0 && gx < WDIM && gy >= 0 && gy < HDIM) {
            int idx = gy * WDIM + gx;
            v = score_fn(rp[idx], up[idx]);
        }
        sc[ly][lx] = v;
    }
    __syncthreads();

    // peak test: score == 3x3 max  <=>  score >= all 8 neighbors
    for (int r = 0; r < 4; r++) {
        int ly = (tid >> 5) + r * 8 + 1;
        int lx = (tid & 31) + 1;
        float v = sc[ly][lx];
        bool peak = v >= sc[ly - 1][lx - 1] && v >= sc[ly - 1][lx] && v >= sc[ly - 1][lx + 1]
                 && v >= sc[ly][lx - 1]                            && v >= sc[ly][lx + 1]
                 && v >= sc[ly + 1][lx - 1] && v >= sc[ly + 1][lx] && v >= sc[ly + 1][lx + 1];
        if (peak) {
            unsigned gx = (unsigned)(tx0 + lx - 1);
            unsigned gy = (unsigned)(ty0 + ly - 1);
            unsigned idx = gy * WDIM + gx;
            // key: descending score, then ascending index on ties (matches jax top_k)
            unsigned long long key =
                ((unsigned long long)__float_as_uint(v) << 32) |
                (unsigned long long)(~idx);
            int p = atomicAdd(&scnt, 1);
            sbuf[p] = key;
        }
    }
    __syncthreads();

    if (tid == 0) sbase = atomicAdd(&g_cnt[b], scnt);
    __syncthreads();

    for (int i = tid; i < scnt; i += 256) {
        int dst = sbase + i;
        if (dst < MAXCAND) g_cand[b][dst] = sbuf[i];
    }
}

// -------- kernel 2: per-batch 64-bit radix select + bitonic sort of top-K --------
__global__ __launch_bounds__(1024) void select_kernel() {
    __shared__ unsigned int hist[256];
    __shared__ unsigned long long skeys[1024];
    __shared__ unsigned long long sh_prefix;
    __shared__ int sh_k;
    __shared__ int sh_n;

    int b = blockIdx.x;
    int tid = threadIdx.x;
    int cnt = g_cnt[b];
    if (cnt > MAXCAND) cnt = MAXCAND;
    int k = (cnt < KTOP) ? cnt : KTOP;

    unsigned long long T = 0ull;
    if (cnt > KTOP) {
        unsigned long long prefix = 0ull;
        int kk = k;
        for (int d = 7; d >= 0; --d) {
            int sh = d * 8;
            for (int i = tid; i < 256; i += 1024) hist[i] = 0u;
            __syncthreads();
            for (int i = tid; i < cnt; i += 1024) {
                unsigned long long key = g_cand[b][i];
                bool match = (d == 7) || ((key >> (sh + 8)) == (prefix >> (sh + 8)));
                if (match) atomicAdd(&hist[(unsigned)(key >> sh) & 255u], 1u);
            }
            __syncthreads();
            if (tid == 0) {
                unsigned acc = 0;
                for (int bin = 255; bin >= 0; --bin) {
                    unsigned c = hist[bin];
                    if (acc + c >= (unsigned)kk) {
                        prefix |= ((unsigned long long)bin) << sh;
                        kk -= (int)acc;
                        break;
                    }
                    acc += c;
                }
                sh_prefix = prefix;
                sh_k = kk;
            }
            __syncthreads();
            prefix = sh_prefix;
            kk = sh_k;
            __syncthreads();
        }
        T = prefix;  // exact k-th largest key (keys are unique)
    }

    // compact keys >= T (exactly k of them when cnt > KTOP; all when cnt <= KTOP)
    if (tid == 0) sh_n = 0;
    skeys[tid] = 0ull;
    __syncthreads();
    for (int i = tid; i < cnt; i += 1024) {
        unsigned long long key = g_cand[b][i];
        if (key >= T) {
            int p = atomicAdd(&sh_n, 1);
            if (p < 1024) skeys[p] = key;
        }
    }
    __syncthreads();

    // bitonic sort ascending (1024 elements, zero padding sorts to front)
    for (int size = 2; size <= 1024; size <<= 1) {
        for (int stride = size >> 1; stride > 0; stride >>= 1) {
            int i = tid;
            int j = i ^ stride;
            if (j > i) {
                bool up = ((i & size) == 0);
                unsigned long long a = skeys[i];
                unsigned long long c = skeys[j];
                if ((a > c) == up) { skeys[i] = c; skeys[j] = a; }
            }
            __syncthreads();
        }
    }

    if (tid < k) g_top[b][tid] = skeys[1023 - tid];  // descending order
    if (tid == 0) g_topk[b] = k;
}

// -------- kernel 3: emit rois / scores / valid --------
__global__ void emit_kernel(const float* __restrict__ scale,
                            const float* __restrict__ unc,
                            const int* __restrict__ p_ih,
                            const int* __restrict__ p_iw,
                            float* __restrict__ out) {
    int t = blockIdx.x * blockDim.x + threadIdx.x;
    if (t >= BATCH * KTOP) return;
    int b = t / KTOP;
    int r = t % KTOP;
    int k = g_topk[b];

    float iw = (float)p_iw[0];
    float ih = (float)p_ih[0];

    float bcol = 0.f, x1 = 0.f, y1 = 0.f, x2 = 0.f, y2 = 0.f, scv = 0.f, vv = 0.f;
    if (r < k) {
        unsigned long long key = g_top[b][r];
        float v = __uint_as_float((unsigned)(key >> 32));
        unsigned idx = ~((unsigned)key);
        int y = (int)(idx / WDIM);
        int x = (int)(idx % WDIM);
        float cx = __fmul_rn(__fadd_rn((float)x, 0.5f), 4.0f);
        float cy = __fmul_rn(__fadd_rn((float)y, 0.5f), 4.0f);
        float sc = scale[(size_t)b * NPIX + idx];
        float un = xla_sigmoidf(unc[(size_t)b * NPIX + idx]);
        float side = __fadd_rn(32.0f, __fmul_rn(xla_sigmoidf(sc), 480.0f));
        side = __fmul_rn(side, __fadd_rn(1.0f, __fmul_rn(0.25f, un)));
        float half = __fmul_rn(side, 0.5f);
        x1 = fminf(fmaxf(__fsub_rn(cx, half), 0.0f), __fsub_rn(iw, 1.0f));
        y1 = fminf(fmaxf(__fsub_rn(cy, half), 0.0f), __fsub_rn(ih, 1.0f));
        x2 = fminf(fmaxf(__fadd_rn(cx, half), 1.0f), iw);
        y2 = fminf(fmaxf(__fadd_rn(cy, half), 1.0f), ih);
        bcol = (float)b;
        scv = v;   // score > 0 always for real peaks -> valid
        vv = 1.0f;
    }

    float* roi = out + (size_t)t * 5;
    roi[0] = bcol; roi[1] = x1; roi[2] = y1; roi[3] = x2; roi[4] = y2;
    out[(size_t)BATCH * KTOP * 5 + t] = scv;   // scores
    out[(size_t)BATCH * KTOP * 6 + t] = vv;    // valid (as 0/1 float)
}

extern "C" void kernel_launch(void* const* d_in, const int* in_sizes, int n_in,
                              void* d_out, int out_size) {
    const float* route = (const float*)d_in[0];
    const float* scale = (const float*)d_in[1];
    const float* uncl  = (const float*)d_in[2];
    const int*   p_ih  = (const int*)d_in[3];
    const int*   p_iw  = (const int*)d_in[4];
    float* out = (float*)d_out;

    zero_cnt_kernel<<<1, 32>>>();

    dim3 grid(WDIM / 32, HDIM / 32, BATCH);
    peaks_kernel<<<grid, 256>>>(route, uncl);

    select_kernel<<<BATCH, 1024>>>();

    int total = BATCH * KTOP;
    emit_kernel<<<(total + 255) / 256, 256>>>(scale, uncl, p_ih, p_iw, out);
}

// round 7
// speedup vs baseline: 1.2348x; 1.2348x over previous
#include <cuda_runtime.h>
#include <cstdint>

#define BATCH 32
#define HDIM 512
#define WDIM 512
#define NPIX (HDIM * WDIM)
#define KTOP 1000
#define MAXCAND 65536
#define DELTA 2e-4f

// -------- static device scratch --------
__device__ unsigned long long g_cand[BATCH][MAXCAND];
__device__ int g_cnt[BATCH];

// -------- XLA:CPU GenerateVF32Exp (Cephes, non-FMA) — bit-exact reference --------
__device__ __forceinline__ float xla_cpu_expf(float x) {
    const float exp_hi = 88.3762626647950f;
    const float exp_lo = -88.3762626647949f;
    const float log2ef = 1.44269504088896341f;
    const float c1 = 0.693359375f;
    const float c2 = -2.12194440e-4f;

    float xc = fminf(fmaxf(x, exp_lo), exp_hi);
    float fx = floorf(__fadd_rn(__fmul_rn(xc, log2ef), 0.5f));
    float tmp = __fmul_rn(c1, fx);
    float z = __fmul_rn(c2, fx);
    float r = __fsub_rn(xc, tmp);
    r = __fsub_rn(r, z);
    z = __fmul_rn(r, r);

    float y = 1.9875691500E-4f;
    y = __fadd_rn(__fmul_rn(y, r), 1.3981999507E-3f);
    y = __fadd_rn(__fmul_rn(y, r), 8.3334519073E-3f);
    y = __fadd_rn(__fmul_rn(y, r), 4.1665795894E-2f);
    y = __fadd_rn(__fmul_rn(y, r), 1.6666665459E-1f);
    y = __fadd_rn(__fmul_rn(y, r), 5.0000001201E-1f);
    y = __fadd_rn(__fmul_rn(y, z), r);
    y = __fadd_rn(y, 1.0f);

    int emm0 = (((int)fx) + 0x7f) << 23;
    return __fmul_rn(y, __int_as_float(emm0));
}

__device__ __forceinline__ float xla_sigmoidf(float x) {
    float e = xla_cpu_expf(-x);
    return __fdiv_rn(1.0f, __fadd_rn(1.0f, e));
}

__device__ __forceinline__ float score_fn(float r, float u) {
    float s  = xla_sigmoidf(r);
    float p  = __fmul_rn(s, s);
    float su = xla_sigmoidf(u);
    float m  = __fsub_rn(1.0f, __fmul_rn(0.35f, su));
    return __fmul_rn(p, m);
}

// cheap approximate score (abs error <~ 1e-5; only used with DELTA margin)
__device__ __forceinline__ float approx_score(float r, float u) {
    float s = __fdividef(1.0f, 1.0f + __expf(-r));
    float m = 1.0f - 0.35f * __fdividef(1.0f, 1.0f + __expf(-u));
    return s * s * m;
}

// -------- kernel 0: reset counters --------
__global__ void zero_cnt_kernel() {
    if (threadIdx.x < BATCH) g_cnt[threadIdx.x] = 0;
}

// -------- kernel 1: approx score + margin NMS + exact rescue + compaction --------
__global__ __launch_bounds__(256) void peaks_kernel(const float* __restrict__ route,
                                                    const float* __restrict__ unc) {
    __shared__ float sr[34][35];
    __shared__ float su_[34][35];
    __shared__ float ap[34][35];
    __shared__ unsigned long long sbuf[1024];
    __shared__ int scnt;
    __shared__ int sbase;

    int b = blockIdx.z;
    int tx0 = blockIdx.x * 32;
    int ty0 = blockIdx.y * 32;
    const float* rp = route + (size_t)b * NPIX;
    const float* up = unc + (size_t)b * NPIX;
    int tid = threadIdx.x;

    if (tid == 0) scnt = 0;

    // stage logits + approx scores for 34x34 halo tile
    for (int i = tid; i < 34 * 34; i += 256) {
        int ly = i / 34, lx = i % 34;
        int gx = tx0 - 1 + lx;
        int gy = ty0 - 1 + ly;
        bool in = (gx >= 0 && gx < WDIM && gy >= 0 && gy < HDIM);
        float r = 0.f, u = 0.f, a = -1e30f;
        if (in) {
            int idx = gy * WDIM + gx;
            r = rp[idx];
            u = up[idx];
            a = approx_score(r, u);
        }
        sr[ly][lx] = r;
        su_[ly][lx] = u;
        ap[ly][lx] = a;
    }
    __syncthreads();

    const int DY[8] = {-1,-1,-1, 0, 0, 1, 1, 1};
    const int DX[8] = {-1, 0, 1,-1, 1,-1, 0, 1};

    for (int rr = 0; rr < 4; rr++) {
        int ly = (tid >> 5) + rr * 8 + 1;
        int lx = (tid & 31) + 1;
        float a = ap[ly][lx];
        bool lose = false;
        unsigned ambm = 0;
        #pragma unroll
        for (int j = 0; j < 8; j++) {
            float nv = ap[ly + DY[j]][lx + DX[j]];
            float d = a - nv;
            if (d < -DELTA) lose = true;
            else if (d <= DELTA) ambm |= (1u << j);
        }
        if (!lose) {
            float v = score_fn(sr[ly][lx], su_[ly][lx]);   // exact (key bits)
            bool peak = true;
            if (ambm) {
                #pragma unroll
                for (int j = 0; j < 8; j++) {
                    if ((ambm >> j) & 1u) {
                        float vn = score_fn(sr[ly + DY[j]][lx + DX[j]],
                                            su_[ly + DY[j]][lx + DX[j]]);
                        if (!(v >= vn)) { peak = false; break; }
                    }
                }
            }
            if (peak) {
                unsigned gx = (unsigned)(tx0 + lx - 1);
                unsigned gy = (unsigned)(ty0 + ly - 1);
                unsigned idx = gy * WDIM + gx;
                unsigned long long key =
                    ((unsigned long long)__float_as_uint(v) << 32) |
                    (unsigned long long)(~idx);
                int p = atomicAdd(&scnt, 1);
                if (p < 1024) sbuf[p] = key;
            }
        }
    }
    __syncthreads();

    int nc = scnt; if (nc > 1024) nc = 1024;
    if (tid == 0) sbase = atomicAdd(&g_cnt[b], nc);
    __syncthreads();

    for (int i = tid; i < nc; i += 256) {
        int dst = sbase + i;
        if (dst < MAXCAND) g_cand[b][dst] = sbuf[i];
    }
}

// -------- device bitonic sort (ascending) on 1024-element smem array --------
__device__ __forceinline__ void bitonic1024(unsigned long long* a, int tid) {
    for (int size = 2; size <= 1024; size <<= 1) {
        for (int stride = size >> 1; stride > 0; stride >>= 1) {
            __syncthreads();
            int j = tid ^ stride;
            if (j > tid) {
                bool up = ((tid & size) == 0);
                unsigned long long x = a[tid];
                unsigned long long y = a[j];
                if ((x > y) == up) { a[tid] = y; a[j] = x; }
            }
        }
    }
    __syncthreads();
}

// -------- kernel 2: two-level radix select + sort + emit, one block per batch --------
__global__ __launch_bounds__(1024) void select_emit_kernel(const float* __restrict__ scale,
                                                           const float* __restrict__ unc,
                                                           const int* __restrict__ p_ih,
                                                           const int* __restrict__ p_iw,
                                                           float* __restrict__ out) {
    __shared__ unsigned int hist[4096];
    __shared__ unsigned int ssum[1024];
    __shared__ unsigned long long skeys[1024];
    __shared__ unsigned long long ties[1024];
    __shared__ int sB1, sB2;
    __shared__ unsigned sGt1, sGt2;
    __shared__ int n_hi;
    __shared__ int n_tie;

    int b = blockIdx.x;
    int tid = threadIdx.x;
    int cnt = g_cnt[b];
    if (cnt > MAXCAND) cnt = MAXCAND;
    int k = (cnt < KTOP) ? cnt : KTOP;

    bool need_sel = (cnt > KTOP);

    if (need_sel) {
        // ---- level 1: histogram over score bits [31:20] ----
        #pragma unroll
        for (int j = 0; j < 4; j++) hist[tid * 4 + j] = 0u;
        __syncthreads();
        for (int i = tid; i < cnt; i += 1024) {
            unsigned sb = (unsigned)(g_cand[b][i] >> 32);
            atomicAdd(&hist[sb >> 20], 1u);
        }
        __syncthreads();

        unsigned tsum = hist[tid * 4] + hist[tid * 4 + 1] + hist[tid * 4 + 2] + hist[tid * 4 + 3];
        ssum[tid] = tsum;
        __syncthreads();
        for (int off = 1; off < 1024; off <<= 1) {
            unsigned v = (tid + off < 1024) ? ssum[tid + off] : 0u;
            __syncthreads();
            ssum[tid] += v;
            __syncthreads();
        }
        {
            unsigned above = (tid + 1 < 1024) ? ssum[tid + 1] : 0u;
            if (above < (unsigned)k && above + tsum >= (unsigned)k) {
                unsigned acc = above;
                for (int j = 3; j >= 0; --j) {
                    unsigned c = hist[tid * 4 + j];
                    if (acc + c >= (unsigned)k) { sB1 = tid * 4 + j; sGt1 = acc; break; }
                    acc += c;
                }
            }
        }
        __syncthreads();

        // ---- level 2: histogram over score bits [19:8], restricted to bin B1 ----
        int B1 = sB1;
        int k2 = k - (int)sGt1;   // >= 1 by construction
        #pragma unroll
        for (int j = 0; j < 4; j++) hist[tid * 4 + j] = 0u;
        __syncthreads();
        for (int i = tid; i < cnt; i += 1024) {
            unsigned sb = (unsigned)(g_cand[b][i] >> 32);
            if ((int)(sb >> 20) == B1) atomicAdd(&hist[(sb >> 8) & 0xFFFu], 1u);
        }
        __syncthreads();

        tsum = hist[tid * 4] + hist[tid * 4 + 1] + hist[tid * 4 + 2] + hist[tid * 4 + 3];
        ssum[tid] = tsum;
        __syncthreads();
        for (int off = 1; off < 1024; off <<= 1) {
            unsigned v = (tid + off < 1024) ? ssum[tid + off] : 0u;
            __syncthreads();
            ssum[tid] += v;
            __syncthreads();
        }
        {
            unsigned above = (tid + 1 < 1024) ? ssum[tid + 1] : 0u;
            if (above < (unsigned)k2 && above + tsum >= (unsigned)k2) {
                unsigned acc = above;
                for (int j = 3; j >= 0; --j) {
                    unsigned c = hist[tid * 4 + j];
                    if (acc + c >= (unsigned)k2) { sB2 = tid * 4 + j; sGt2 = acc; break; }
                    acc += c;
                }
            }
        }
        __syncthreads();
    }

    // init compaction buffers
    if (tid == 0) { n_hi = 0; n_tie = 0; }
    skeys[tid] = 0ull;
    ties[tid] = 0ull;
    __syncthreads();

    if (need_sel) {
        int B1 = sB1, B2 = sB2;
        // compact: hi = strictly greater at level1 or level2; tie = equal at both
        for (int i = tid; i < cnt; i += 1024) {
            unsigned long long key = g_cand[b][i];
            unsigned sb = (unsigned)(key >> 32);
            int t12 = (int)(sb >> 20);
            if (t12 > B1) {
                int p = atomicAdd(&n_hi, 1);
                skeys[p] = key;                         // n_hi_total = gt1+gt2 <= k-1 < 1024
            } else if (t12 == B1) {
                int m12 = (int)((sb >> 8) & 0xFFFu);
                if (m12 > B2) {
                    int p = atomicAdd(&n_hi, 1);
                    skeys[p] = key;
                } else if (m12 == B2) {
                    int p = atomicAdd(&n_tie, 1);
                    if (p < 1024) ties[p] = key;        // ~24-bit refined: expected O(1) ties
                }
            }
        }
        __syncthreads();
        // sort boundary ties, append top (k - gt1 - gt2)
        bitonic1024(ties, tid);
        int gt = (int)sGt1 + (int)sGt2;
        int r = k - gt;
        if (tid < r) skeys[gt + tid] = ties[1023 - tid];
        __syncthreads();
    } else {
        for (int i = tid; i < cnt; i += 1024) {
            int p = atomicAdd(&n_hi, 1);
            skeys[p] = g_cand[b][i];                    // cnt <= 1000
        }
        __syncthreads();
    }

    // final sort (ascending, zero pad to front)
    bitonic1024(skeys, tid);

    // emit rows for this batch
    if (tid < KTOP) {
        float iw = (float)p_iw[0];
        float ih = (float)p_ih[0];
        float bcol = 0.f, x1 = 0.f, y1 = 0.f, x2 = 0.f, y2 = 0.f, scv = 0.f, vv = 0.f;
        if (tid < k) {
            unsigned long long key = skeys[1023 - tid];
            float v = __uint_as_float((unsigned)(key >> 32));
            unsigned idx = ~((unsigned)key);
            int y = (int)(idx / WDIM);
            int x = (int)(idx % WDIM);
            float cx = __fmul_rn(__fadd_rn((float)x, 0.5f), 4.0f);
            float cy = __fmul_rn(__fadd_rn((float)y, 0.5f), 4.0f);
            float sc = scale[(size_t)b * NPIX + idx];
            float un = xla_sigmoidf(unc[(size_t)b * NPIX + idx]);
            float side = __fadd_rn(32.0f, __fmul_rn(xla_sigmoidf(sc), 480.0f));
            side = __fmul_rn(side, __fadd_rn(1.0f, __fmul_rn(0.25f, un)));
            float half = __fmul_rn(side, 0.5f);
            x1 = fminf(fmaxf(__fsub_rn(cx, half), 0.0f), __fsub_rn(iw, 1.0f));
            y1 = fminf(fmaxf(__fsub_rn(cy, half), 0.0f), __fsub_rn(ih, 1.0f));
            x2 = fminf(fmaxf(__fadd_rn(cx, half), 1.0f), iw);
            y2 = fminf(fmaxf(__fadd_rn(cy, half), 1.0f), ih);
            bcol = (float)b;
            scv = v;
            vv = 1.0f;
        }
        int t = b * KTOP + tid;
        float* roi = out + (size_t)t * 5;
        roi[0] = bcol; roi[1] = x1; roi[2] = y1; roi[3] = x2; roi[4] = y2;
        out[(size_t)BATCH * KTOP * 5 + t] = scv;
        out[(size_t)BATCH * KTOP * 6 + t] = vv;
    }
}

extern "C" void kernel_launch(void* const* d_in, const int* in_sizes, int n_in,
                              void* d_out, int out_size) {
    const float* route = (const float*)d_in[0];
    const float* scale = (const float*)d_in[1];
    const float* uncl  = (const float*)d_in[2];
    const int*   p_ih  = (const int*)d_in[3];
    const int*   p_iw  = (const int*)d_in[4];
    float* out = (float*)d_out;

    zero_cnt_kernel<<<1, 32>>>();

    dim3 grid(WDIM / 32, HDIM / 32, BATCH);
    peaks_kernel<<<grid, 256>>>(route, uncl);

    select_emit_kernel<<<BATCH, 1024>>>(scale, uncl, p_ih, p_iw, out);
}

// round 9
// speedup vs baseline: 1.3910x; 1.1265x over previous
#include <cuda_runtime.h>
#include <cstdint>

#define BATCH 32
#define HDIM 512
#define WDIM 512
#define NPIX (HDIM * WDIM)
#define KTOP 1000
#define KPRIME (KTOP + 512)
#define NTILES 256
#define MAXTILE 256
#define DELTA 2e-4f

// -------- static device scratch --------
__device__ unsigned long long g_tile[BATCH][NTILES][MAXTILE];
__device__ int g_tcnt[BATCH][NTILES];
__device__ unsigned long long g_lin[BATCH][65536];

// -------- XLA:CPU GenerateVF32Exp (Cephes, non-FMA) — bit-exact reference --------
__device__ __forceinline__ float xla_cpu_expf(float x) {
    const float exp_hi = 88.3762626647950f;
    const float exp_lo = -88.3762626647949f;
    const float log2ef = 1.44269504088896341f;
    const float c1 = 0.693359375f;
    const float c2 = -2.12194440e-4f;

    float xc = fminf(fmaxf(x, exp_lo), exp_hi);
    float fx = floorf(__fadd_rn(__fmul_rn(xc, log2ef), 0.5f));
    float tmp = __fmul_rn(c1, fx);
    float z = __fmul_rn(c2, fx);
    float r = __fsub_rn(xc, tmp);
    r = __fsub_rn(r, z);
    z = __fmul_rn(r, r);

    float y = 1.9875691500E-4f;
    y = __fadd_rn(__fmul_rn(y, r), 1.3981999507E-3f);
    y = __fadd_rn(__fmul_rn(y, r), 8.3334519073E-3f);
    y = __fadd_rn(__fmul_rn(y, r), 4.1665795894E-2f);
    y = __fadd_rn(__fmul_rn(y, r), 1.6666665459E-1f);
    y = __fadd_rn(__fmul_rn(y, r), 5.0000001201E-1f);
    y = __fadd_rn(__fmul_rn(y, z), r);
    y = __fadd_rn(y, 1.0f);

    int emm0 = (((int)fx) + 0x7f) << 23;
    return __fmul_rn(y, __int_as_float(emm0));
}

__device__ __forceinline__ float xla_sigmoidf(float x) {
    float e = xla_cpu_expf(-x);
    return __fdiv_rn(1.0f, __fadd_rn(1.0f, e));
}

__device__ __forceinline__ float score_fn(float r, float u) {
    float s  = xla_sigmoidf(r);
    float p  = __fmul_rn(s, s);
    float su = xla_sigmoidf(u);
    float m  = __fsub_rn(1.0f, __fmul_rn(0.35f, su));
    return __fmul_rn(p, m);
}

// cheap approximate score; |approx - exact| <= ~1e-6 << DELTA
__device__ __forceinline__ float approx_score(float r, float u) {
    float s = __fdividef(1.0f, 1.0f + __expf(-r));
    float m = 1.0f - 0.35f * __fdividef(1.0f, 1.0f + __expf(-u));
    return s * s * m;
}

// -------- kernel 1: approx score + margin NMS -> per-tile candidates --------
__global__ __launch_bounds__(256) void peaks_kernel(const float* __restrict__ route,
                                                    const float* __restrict__ unc) {
    __shared__ float ap[34][35];
    __shared__ unsigned long long sbuf[MAXTILE];
    __shared__ int scnt;

    int b = blockIdx.z;
    int tileId = blockIdx.y * 16 + blockIdx.x;
    int tx0 = blockIdx.x * 32;
    int ty0 = blockIdx.y * 32;
    const float* rp = route + (size_t)b * NPIX;
    const float* up = unc + (size_t)b * NPIX;
    int tid = threadIdx.x;

    if (tid == 0) scnt = 0;

    for (int i = tid; i < 34 * 34; i += 256) {
        int ly = i / 34, lx = i % 34;
        int gx = tx0 - 1 + lx;
        int gy = ty0 - 1 + ly;
        float a = -1e30f;
        if (gx >= 0 && gx < WDIM && gy >= 0 && gy < HDIM) {
            int idx = (gy << 9) | gx;
            a = approx_score(rp[idx], up[idx]);
        }
        ap[ly][lx] = a;
    }
    __syncthreads();

    const int DY[8] = {-1,-1,-1, 0, 0, 1, 1, 1};
    const int DX[8] = {-1, 0, 1,-1, 1,-1, 0, 1};

    for (int rr = 0; rr < 4; rr++) {
        int ly = (tid >> 5) + rr * 8 + 1;
        int lx = (tid & 31) + 1;
        float a = ap[ly][lx];
        bool lose = false;
        bool amb = false;
        #pragma unroll
        for (int j = 0; j < 8; j++) {
            float d = a - ap[ly + DY[j]][lx + DX[j]];
            if (d < -DELTA) lose = true;
            else if (d <= DELTA) amb = true;
        }
        if (!lose) {
            unsigned idx = (unsigned)(((ty0 + ly - 1) << 9) | (tx0 + lx - 1));
            unsigned lo = idx | (amb ? 0x80000000u : 0u);
            unsigned long long key =
                ((unsigned long long)__float_as_uint(a) << 32) | (unsigned long long)lo;
            int p = atomicAdd(&scnt, 1);
            if (p < MAXTILE) sbuf[p] = key;
        }
    }
    __syncthreads();

    int nc = scnt; if (nc > MAXTILE) nc = MAXTILE;
    if (tid == 0) g_tcnt[b][tileId] = nc;
    for (int i = tid; i < nc; i += 256) g_tile[b][tileId][i] = sbuf[i];
}

// -------- bitonic sort (ascending) on 2048-element smem array, 1024 threads --------
__device__ __forceinline__ void bitonic2048(unsigned long long* a, int tid) {
    for (int size = 2; size <= 2048; size <<= 1) {
        for (int stride = size >> 1; stride > 0; stride >>= 1) {
            __syncthreads();
            #pragma unroll
            for (int h = 0; h < 2; h++) {
                int i = tid + h * 1024;
                int j = i ^ stride;
                if (j > i) {
                    bool up = ((i & size) == 0);
                    unsigned long long x = a[i];
                    unsigned long long y = a[j];
                    if ((x > y) == up) { a[i] = y; a[j] = x; }
                }
            }
        }
    }
    __syncthreads();
}

// -------- kernel 2: gather + approx top-K' + exact rescore + sort + emit --------
__global__ __launch_bounds__(1024) void select_emit_kernel(const float* __restrict__ route,
                                                           const float* __restrict__ unc,
                                                           const float* __restrict__ scale,
                                                           const int* __restrict__ p_ih,
                                                           const int* __restrict__ p_iw,
                                                           float* __restrict__ out) {
    __shared__ unsigned int hist[4096];
    __shared__ unsigned int ssum[1024];
    __shared__ unsigned int P[NTILES + 1];
    __shared__ unsigned long long skeys[2048];
    __shared__ int sB1, sB2;
    __shared__ unsigned sGt1;
    __shared__ int n_sel;
    __shared__ int n_valid;

    int b = blockIdx.x;
    int tid = threadIdx.x;
    int wid = tid >> 5, lane = tid & 31;

    // ---- phase A: prefix over tile counts, compact into g_lin ----
    if (tid < NTILES) ssum[tid] = (unsigned)g_tcnt[b][tid];
    __syncthreads();
    for (int off = 1; off < NTILES; off <<= 1) {
        unsigned v = 0;
        if (tid < NTILES && tid >= off) v = ssum[tid - off];
        __syncthreads();
        if (tid < NTILES) ssum[tid] += v;
        __syncthreads();
    }
    if (tid < NTILES) P[tid + 1] = ssum[tid];
    if (tid == 0) P[0] = 0;
    __syncthreads();
    int cnt = (int)P[NTILES];

    for (int t = wid; t < NTILES; t += 32) {
        int n = g_tcnt[b][t];
        unsigned base = P[t];
        for (int i = lane; i < n; i += 32)
            g_lin[b][base + i] = g_tile[b][t][i];
    }
    __syncthreads();

    bool need_sel = (cnt > KPRIME);

    if (need_sel) {
        // ---- level 1: histogram over approx bits [31:20], target rank KPRIME ----
        #pragma unroll
        for (int j = 0; j < 4; j++) hist[tid * 4 + j] = 0u;
        __syncthreads();
        for (int i = tid; i < cnt; i += 1024) {
            unsigned sb = (unsigned)(g_lin[b][i] >> 32);
            atomicAdd(&hist[sb >> 20], 1u);
        }
        __syncthreads();

        unsigned tsum = hist[tid * 4] + hist[tid * 4 + 1] + hist[tid * 4 + 2] + hist[tid * 4 + 3];
        ssum[tid] = tsum;
        __syncthreads();
        for (int off = 1; off < 1024; off <<= 1) {
            unsigned v = (tid + off < 1024) ? ssum[tid + off] : 0u;
            __syncthreads();
            ssum[tid] += v;
            __syncthreads();
        }
        {
            unsigned above = (tid + 1 < 1024) ? ssum[tid + 1] : 0u;
            if (above < (unsigned)KPRIME && above + tsum >= (unsigned)KPRIME) {
                unsigned acc = above;
                for (int j = 3; j >= 0; --j) {
                    unsigned c = hist[tid * 4 + j];
                    if (acc + c >= (unsigned)KPRIME) { sB1 = tid * 4 + j; sGt1 = acc; break; }
                    acc += c;
                }
            }
        }
        __syncthreads();

        // ---- level 2: bits [19:8] within boundary bin B1 ----
        int B1 = sB1;
        int k2 = KPRIME - (int)sGt1;
        #pragma unroll
        for (int j = 0; j < 4; j++) hist[tid * 4 + j] = 0u;
        __syncthreads();
        for (int i = tid; i < cnt; i += 1024) {
            unsigned sb = (unsigned)(g_lin[b][i] >> 32);
            if ((int)(sb >> 20) == B1) atomicAdd(&hist[(sb >> 8) & 0xFFFu], 1u);
        }
        __syncthreads();

        tsum = hist[tid * 4] + hist[tid * 4 + 1] + hist[tid * 4 + 2] + hist[tid * 4 + 3];
        ssum[tid] = tsum;
        __syncthreads();
        for (int off = 1; off < 1024; off <<= 1) {
            unsigned v = (tid + off < 1024) ? ssum[tid + off] : 0u;
            __syncthreads();
            ssum[tid] += v;
            __syncthreads();
        }
        {
            unsigned above = (tid + 1 < 1024) ? ssum[tid + 1] : 0u;
            if (above < (unsigned)k2 && above + tsum >= (unsigned)k2) {
                unsigned acc = above;
                for (int j = 3; j >= 0; --j) {
                    unsigned c = hist[tid * 4 + j];
                    if (acc + c >= (unsigned)k2) { sB2 = tid * 4 + j; break; }
                    acc += c;
                }
            }
        }
        __syncthreads();
    }

    // ---- phase C: compact selected (approx >= refined boundary) ----
    if (tid == 0) { n_sel = 0; n_valid = 0; }
    skeys[tid] = 0ull;
    skeys[tid + 1024] = 0ull;
    __syncthreads();

    if (need_sel) {
        int B1 = sB1, B2 = sB2;
        for (int i = tid; i < cnt; i += 1024) {
            unsigned long long key = g_lin[b][i];
            unsigned sb = (unsigned)(key >> 32);
            int t12 = (int)(sb >> 20);
            bool take = (t12 > B1) ||
                        (t12 == B1 && (int)((sb >> 8) & 0xFFFu) >= B2);
            if (take) {
                int p = atomicAdd(&n_sel, 1);
                if (p < 2048) skeys[p] = key;
            }
        }
    } else {
        for (int i = tid; i < cnt; i += 1024) skeys[i] = g_lin[b][i];  // cnt <= KPRIME
    }
    __syncthreads();

    // ---- phase D: exact rescore of selected; resolve ambiguous peaks exactly ----
    const float* rp = route + (size_t)b * NPIX;
    const float* up = unc + (size_t)b * NPIX;
    const int DY[8] = {-1,-1,-1, 0, 0, 1, 1, 1};
    const int DX[8] = {-1, 0, 1,-1, 1,-1, 0, 1};

    #pragma unroll
    for (int h = 0; h < 2; h++) {
        int i = tid + h * 1024;
        unsigned long long key = skeys[i];
        unsigned long long nk = 0ull;
        if (key != 0ull) {
            unsigned lo = (unsigned)key;
            unsigned idx = lo & 0x3FFFFu;
            bool amb = (lo >> 31) != 0u;
            float v = score_fn(rp[idx], up[idx]);
            bool ok = true;
            if (amb) {
                int y = (int)(idx >> 9), x = (int)(idx & 511);
                #pragma unroll
                for (int j = 0; j < 8; j++) {
                    int nx = x + DX[j], ny = y + DY[j];
                    if (nx >= 0 && nx < WDIM && ny >= 0 && ny < HDIM) {
                        int nidx = (ny << 9) | nx;
                        float vn = score_fn(rp[nidx], up[nidx]);
                        if (!(v >= vn)) { ok = false; break; }
                    }
                }
            }
            if (ok) {
                nk = ((unsigned long long)__float_as_uint(v) << 32) |
                     (unsigned long long)(~idx);
                atomicAdd(&n_valid, 1);
            }
        }
        skeys[i] = nk;
    }
    __syncthreads();

    // ---- phase E: exact sort, take top KTOP ----
    bitonic2048(skeys, tid);

    int k = n_valid; if (k > KTOP) k = KTOP;

    // ---- phase F: emit ----
    if (tid < KTOP) {
        float iw = (float)p_iw[0];
        float ih = (float)p_ih[0];
        float bcol = 0.f, x1 = 0.f, y1 = 0.f, x2 = 0.f, y2 = 0.f, scv = 0.f, vv = 0.f;
        if (tid < k) {
            unsigned long long key = skeys[2047 - tid];
            float v = __uint_as_float((unsigned)(key >> 32));
            unsigned idx = (~((unsigned)key)) & 0x3FFFFu;
            int y = (int)(idx >> 9);
            int x = (int)(idx & 511);
            float cx = __fmul_rn(__fadd_rn((float)x, 0.5f), 4.0f);
            float cy = __fmul_rn(__fadd_rn((float)y, 0.5f), 4.0f);
            float sc = scale[(size_t)b * NPIX + idx];
            float un = xla_sigmoidf(up[idx]);
            float side = __fadd_rn(32.0f, __fmul_rn(xla_sigmoidf(sc), 480.0f));
            side = __fmul_rn(side, __fadd_rn(1.0f, __fmul_rn(0.25f, un)));
            float half = __fmul_rn(side, 0.5f);
            x1 = fminf(fmaxf(__fsub_rn(cx, half), 0.0f), __fsub_rn(iw, 1.0f));
            y1 = fminf(fmaxf(__fsub_rn(cy, half), 0.0f), __fsub_rn(ih, 1.0f));
            x2 = fminf(fmaxf(__fadd_rn(cx, half), 1.0f), iw);
            y2 = fminf(fmaxf(__fadd_rn(cy, half), 1.0f), ih);
            bcol = (float)b;
            scv = v;
            vv = 1.0f;
        }
        int t = b * KTOP + tid;
        float* roi = out + (size_t)t * 5;
        roi[0] = bcol; roi[1] = x1; roi[2] = y1; roi[3] = x2; roi[4] = y2;
        out[(size_t)BATCH * KTOP * 5 + t] = scv;
        out[(size_t)BATCH * KTOP * 6 + t] = vv;
    }
}

extern "C" void kernel_launch(void* const* d_in, const int* in_sizes, int n_in,
                              void* d_out, int out_size) {
    const float* route = (const float*)d_in[0];
    const float* scale = (const float*)d_in[1];
    const float* uncl  = (const float*)d_in[2];
    const int*   p_ih  = (const int*)d_in[3];
    const int*   p_iw  = (const int*)d_in[4];
    float* out = (float*)d_out;

    dim3 grid(WDIM / 32, HDIM / 32, BATCH);
    peaks_kernel<<<grid, 256>>>(route, uncl);

    select_emit_kernel<<<BATCH, 1024>>>(route, uncl, scale, p_ih, p_iw, out);
}